// round 16
// baseline (speedup 1.0000x reference)
#include <cuda_runtime.h>
#include <cuda_fp16.h>
#include <cstdint>

// out = concat(x, y, outer(x,y)) @ W^T, two kernels:
//  1) lin_pipe  : k < 1024 passthrough (proven).
//  2) quad_frag : bilinear FACTORIZED (out += sum_i x_i * (y @ W_i^T)).
//     THIS ROUND: W fragments are LDG'd DIRECTLY from gmem into the
//     mma.m16n8k16 B-fragment lanes (coalesced LDG.64 pairs), cvt'd to fp16
//     in registers. No W smem stage, no STS/ldmatrix for W, and NO per-stage
//     __syncthreads -- warps run decoupled; only the x-slab restage (every
//     64 i) synchronizes. Same values & per-element op order as the 2507us
//     kernel -> rel_err must stay bit-identical 4.137952e-4.

namespace {

constexpr int    kN1  = 512;
constexpr int    kOUT = 1024;
constexpr size_t kK   = 263168;

__device__ __forceinline__ uint32_t smem_u32(const void* p) {
  uint32_t a;
  asm("{ .reg .u64 t; cvta.to.shared.u64 t, %1; cvt.u32.u64 %0, t; }"
      : "=r"(a) : "l"(p));
  return a;
}
__device__ __forceinline__ void ldx4(uint32_t r[4], uint32_t addr) {
  asm volatile(
      "ldmatrix.sync.aligned.m8n8.x4.shared.b16 {%0,%1,%2,%3}, [%4];"
      : "=r"(r[0]), "=r"(r[1]), "=r"(r[2]), "=r"(r[3]) : "r"(addr));
}
__device__ __forceinline__ void mma16(float c[4], const uint32_t a[4],
                                      uint32_t b0, uint32_t b1) {
  asm volatile(
      "mma.sync.aligned.m16n8k16.row.col.f32.f16.f16.f32 "
      "{%0,%1,%2,%3}, {%4,%5,%6,%7}, {%8,%9}, {%0,%1,%2,%3};"
      : "+f"(c[0]), "+f"(c[1]), "+f"(c[2]), "+f"(c[3])
      : "r"(a[0]), "r"(a[1]), "r"(a[2]), "r"(a[3]), "r"(b0), "r"(b1));
}
__device__ __forceinline__ void sts128(uint32_t a, uint32_t v0, uint32_t v1,
                                       uint32_t v2, uint32_t v3) {
  asm volatile("st.shared.v4.b32 [%0], {%1,%2,%3,%4};"
               :: "r"(a), "r"(v0), "r"(v1), "r"(v2), "r"(v3) : "memory");
}
__device__ __forceinline__ void sts32(uint32_t a, float v) {
  asm volatile("st.shared.f32 [%0], %1;" :: "r"(a), "f"(v) : "memory");
}
__device__ __forceinline__ float lds32(uint32_t a) {
  float v;
  asm volatile("ld.shared.f32 %0, [%1];" : "=f"(v) : "r"(a));
  return v;
}
__device__ __forceinline__ uint32_t pack_h2(float v0, float v1) {
  __half2 h = __floats2half2_rn(v0, v1);
  return *reinterpret_cast<uint32_t*>(&h);
}
__device__ __forceinline__ void split_h2(float v0, float v1, uint32_t& h,
                                         uint32_t& l) {
  __half2 hh = __floats2half2_rn(v0, v1);
  h = *reinterpret_cast<uint32_t*>(&hh);
  l = pack_h2(v0 - __low2float(hh), v1 - __high2float(hh));
}
__device__ __forceinline__ uint32_t dup_h2(float f) {
  __half2 h = __half2half2(__float2half_rn(f));
  return *reinterpret_cast<uint32_t*>(&h);
}
__device__ __forceinline__ uint32_t hmul2u(uint32_t a, uint32_t b) {
  __half2 r = __hmul2(*reinterpret_cast<__half2*>(&a),
                      *reinterpret_cast<__half2*>(&b));
  return *reinterpret_cast<uint32_t*>(&r);
}

// ======================= linear part (k<1024): proven pipeline ==============
constexpr int L_LDA = 80, L_SZA = 128 * L_LDA, L_SZW = 128 * L_LDA;
constexpr int L_STAGE = L_SZA + 2 * L_SZW;
constexpr int LNH = 16;

__global__ void __launch_bounds__(256, 1)
lin_pipe(const float* __restrict__ x, const float* __restrict__ y,
         const float* __restrict__ W, float* __restrict__ out) {
  __shared__ __align__(16) uint8_t sm[2 * L_STAGE];
  const uint32_t sb = smem_u32(sm);

  const int tid = threadIdx.x, lane = tid & 31, warp = tid >> 5;
  const int wm = warp >> 2, wn = warp & 3;
  const int b0 = (blockIdx.x >> 1) * 128;
  const int half = blockIdx.x & 1;
  const int o0 = blockIdx.y * 128;
  const int gbase = half * LNH;

  const int prow = tid >> 1, phh = tid & 1;
  const float* __restrict__ xrow = x + (size_t)(b0 + prow) * kN1;
  const float* __restrict__ yrow = y + (size_t)(b0 + prow) * kN1;
  const float* __restrict__ wsrc = W + (size_t)(o0 + prow) * kK + phh * 16;
  const uint32_t pSt = prow * L_LDA + phh * 32;

  const uint32_t aoff =
      (uint32_t)((wm * 64 + (lane & 15)) * L_LDA + (lane >> 4) * 16);
  const uint32_t boff =
      (uint32_t)((wn * 32 + (lane & 7) + ((lane >> 4) & 1) * 8) * L_LDA +
                 ((lane >> 3) & 1) * 16);
  const int g = lane >> 2, t = lane & 3;

  float acc[4][4][4];
#pragma unroll
  for (int mt = 0; mt < 4; mt++)
#pragma unroll
    for (int nt = 0; nt < 4; nt++)
#pragma unroll
      for (int r = 0; r < 4; r++) acc[mt][nt][r] = 0.f;

  float4 av[4], wv[4];

  {  // chunk 0 into stage 0
    const int gc = gbase;
    const float* asrc = (gc < 16) ? (xrow + gc * 32 + phh * 16)
                                  : (yrow + (gc - 16) * 32 + phh * 16);
#pragma unroll
    for (int j = 0; j < 4; j++) av[j] = *(const float4*)(asrc + 4 * j);
    const float* wp = wsrc + (size_t)gc * 32;
#pragma unroll
    for (int j = 0; j < 4; j++) wv[j] = *(const float4*)(wp + 4 * j);

    uint32_t pA[8], pWh[8], pWl[8];
#pragma unroll
    for (int j = 0; j < 4; j++) {
      pA[2 * j]     = pack_h2(av[j].x, av[j].y);
      pA[2 * j + 1] = pack_h2(av[j].z, av[j].w);
      split_h2(wv[j].x, wv[j].y, pWh[2 * j], pWl[2 * j]);
      split_h2(wv[j].z, wv[j].w, pWh[2 * j + 1], pWl[2 * j + 1]);
    }
    sts128(sb + pSt, pA[0], pA[1], pA[2], pA[3]);
    sts128(sb + pSt + 16, pA[4], pA[5], pA[6], pA[7]);
    sts128(sb + L_SZA + pSt, pWh[0], pWh[1], pWh[2], pWh[3]);
    sts128(sb + L_SZA + pSt + 16, pWh[4], pWh[5], pWh[6], pWh[7]);
    sts128(sb + L_SZA + L_SZW + pSt, pWl[0], pWl[1], pWl[2], pWl[3]);
    sts128(sb + L_SZA + L_SZW + pSt + 16, pWl[4], pWl[5], pWl[6], pWl[7]);
  }
  __syncthreads();

  for (int ic = 0; ic < LNH; ic++) {
    const uint32_t rs = sb + (uint32_t)(ic & 1) * L_STAGE;
    const uint32_t ws = sb + (uint32_t)((ic + 1) & 1) * L_STAGE;
    const bool more = (ic + 1 < LNH);

    if (more) {
      const int gc = gbase + ic + 1;
      const float* asrc = (gc < 16) ? (xrow + gc * 32 + phh * 16)
                                    : (yrow + (gc - 16) * 32 + phh * 16);
#pragma unroll
      for (int j = 0; j < 4; j++) av[j] = *(const float4*)(asrc + 4 * j);
      const float* wp = wsrc + (size_t)gc * 32;
#pragma unroll
      for (int j = 0; j < 4; j++) wv[j] = *(const float4*)(wp + 4 * j);
    }

#pragma unroll
    for (int ks = 0; ks < 2; ks++) {
      const uint32_t ko = ks * 32;
      uint32_t aH[4][4], bH[2][4], bL[2][4];
#pragma unroll
      for (int mt = 0; mt < 4; mt++)
        ldx4(aH[mt], rs + aoff + mt * (16 * L_LDA) + ko);
#pragma unroll
      for (int p = 0; p < 2; p++) {
        ldx4(bH[p], rs + L_SZA + boff + p * (16 * L_LDA) + ko);
        ldx4(bL[p], rs + L_SZA + L_SZW + boff + p * (16 * L_LDA) + ko);
      }
#pragma unroll
      for (int mt = 0; mt < 4; mt++)
#pragma unroll
        for (int nt = 0; nt < 4; nt++) {
          const int p = nt >> 1, o = (nt & 1) * 2;
          mma16(acc[mt][nt], aH[mt], bH[p][o], bH[p][o + 1]);
          mma16(acc[mt][nt], aH[mt], bL[p][o], bL[p][o + 1]);
        }
    }

    if (more) {
      uint32_t pA[8], pWh[8], pWl[8];
#pragma unroll
      for (int j = 0; j < 4; j++) {
        pA[2 * j]     = pack_h2(av[j].x, av[j].y);
        pA[2 * j + 1] = pack_h2(av[j].z, av[j].w);
        split_h2(wv[j].x, wv[j].y, pWh[2 * j], pWl[2 * j]);
        split_h2(wv[j].z, wv[j].w, pWh[2 * j + 1], pWl[2 * j + 1]);
      }
      sts128(ws + pSt, pA[0], pA[1], pA[2], pA[3]);
      sts128(ws + pSt + 16, pA[4], pA[5], pA[6], pA[7]);
      sts128(ws + L_SZA + pSt, pWh[0], pWh[1], pWh[2], pWh[3]);
      sts128(ws + L_SZA + pSt + 16, pWh[4], pWh[5], pWh[6], pWh[7]);
      sts128(ws + L_SZA + L_SZW + pSt, pWl[0], pWl[1], pWl[2], pWl[3]);
      sts128(ws + L_SZA + L_SZW + pSt + 16, pWl[4], pWl[5], pWl[6], pWl[7]);
    }
    __syncthreads();
  }

#pragma unroll
  for (int mt = 0; mt < 4; mt++)
#pragma unroll
    for (int nt = 0; nt < 4; nt++) {
      const int r0 = b0 + wm * 64 + mt * 16 + g;
      const int c0 = o0 + wn * 32 + nt * 8 + 2 * t;
      atomicAdd(out + (size_t)r0 * kOUT + c0, acc[mt][nt][0]);
      atomicAdd(out + (size_t)r0 * kOUT + c0 + 1, acc[mt][nt][1]);
      atomicAdd(out + (size_t)(r0 + 8) * kOUT + c0, acc[mt][nt][2]);
      atomicAdd(out + (size_t)(r0 + 8) * kOUT + c0 + 1, acc[mt][nt][3]);
    }
}

// ===== bilinear: factorized, BM=128, 512 thr, W fragments via direct LDG ====
constexpr int F_LDY  = 1040;
constexpr int F_YH   = 128 * F_LDY;        // 133120
constexpr int F_XS   = 64 * 512;           // 32768 (64 i x 128 rows fp32)
constexpr int F_SMEM = F_YH + F_XS;        // 165888

__global__ void __launch_bounds__(512, 1)
quad_frag(const float* __restrict__ x, const float* __restrict__ y,
          const float* __restrict__ W, float* __restrict__ out) {
  extern __shared__ __align__(16) uint8_t dsm[];
  const uint32_t sY = smem_u32(dsm);
  const uint32_t sX = sY + F_YH;

  const int tid = threadIdx.x, lane = tid & 31, warp = tid >> 5;
  const int wm = warp & 3, wn = warp >> 2;  // 4m x 4n, warp tile 32x16
  const int b0 = blockIdx.x * 128, o0 = blockIdx.y * 64;
  const int g = lane >> 2, t = lane & 3;

  // ---- stage Y as fp16 (once) ----
  {
    const int row = tid >> 2, h = tid & 3;
    const float* yr = y + (size_t)(b0 + row) * kN1 + h * 128;
    const uint32_t st = sY + row * F_LDY + h * 256;
#pragma unroll 4
    for (int c = 0; c < 128; c += 8) {
      float4 f0 = *(const float4*)(yr + c);
      float4 f1 = *(const float4*)(yr + c + 4);
      sts128(st + c * 2, pack_h2(f0.x, f0.y), pack_h2(f0.z, f0.w),
             pack_h2(f1.x, f1.y), pack_h2(f1.z, f1.w));
    }
  }

  // ---- x-slab staging: 4 threads/row, 16 i each (fp32, as R14) ----
  const int xrw = tid >> 2, xih = tid & 3;
  const float* __restrict__ xbase = x + (size_t)(b0 + xrw) * kN1 + xih * 16;
  {
#pragma unroll
    for (int j = 0; j < 16; j += 4) {
      float4 v = *(const float4*)(xbase + j);
      const uint32_t a = sX + (xih * 16 + j) * 512 + xrw * 4;
      sts32(a, v.x); sts32(a + 512, v.y); sts32(a + 1024, v.z); sts32(a + 1536, v.w);
    }
  }
  __syncthreads();

  // ---- W fragment pointers: B-frag of m16n8k16 loads straight from gmem ----
  // thread (g,t): rows o0+wn*16+nt*8+g, k-cols 2t,2t+1 (b0) / 2t+8,2t+9 (b1)
  const float* __restrict__ wp0 =
      W + (size_t)(o0 + wn * 16 + g) * kK + 1024 + 2 * t;
  const float* __restrict__ wp1 = wp0 + (size_t)8 * kK;

  const uint32_t aoff =
      (uint32_t)((wm * 32 + (lane & 15)) * F_LDY + (lane >> 4) * 16);

  float acc[2][2][4], tot[2][2][4];
#pragma unroll
  for (int mt = 0; mt < 2; mt++)
#pragma unroll
    for (int nt = 0; nt < 2; nt++)
#pragma unroll
      for (int r = 0; r < 4; r++) { acc[mt][nt][r] = 0.f; tot[mt][nt][r] = 0.f; }

  uint32_t yf[2][4][4];  // Y fragments for current j-block
  uint32_t bc[16];       // current-c W fragments: [ks][nt*2 + b01]
  float2 pv[8];          // half-c prefetch staging

  // ---- prologue: load c=0 fragments directly ----
#pragma unroll
  for (int ks = 0; ks < 4; ks++) {
    float2 a0 = *(const float2*)(wp0 + ks * 16);
    float2 a1 = *(const float2*)(wp0 + ks * 16 + 8);
    float2 a2 = *(const float2*)(wp1 + ks * 16);
    float2 a3 = *(const float2*)(wp1 + ks * 16 + 8);
    bc[ks * 4 + 0] = pack_h2(a0.x, a0.y);
    bc[ks * 4 + 1] = pack_h2(a1.x, a1.y);
    bc[ks * 4 + 2] = pack_h2(a2.x, a2.y);
    bc[ks * 4 + 3] = pack_h2(a3.x, a3.y);
  }

  for (int c = 0; c < 4096; c++) {
    const int i = c & 511;

    if (i == 0) {  // new j-block: reload Y fragments (sY static after init)
      const int jb = c >> 9;
#pragma unroll
      for (int mt = 0; mt < 2; mt++)
#pragma unroll
        for (int ks = 0; ks < 4; ks++)
          ldx4(yf[mt][ks], sY + aoff + jb * 128 + mt * (16 * F_LDY) + ks * 32);
    }
    if ((c & 63) == 0 && c) {  // restage x-slab (barrier pair, 63 total)
      __syncthreads();
      const int iblk = i >> 6;
#pragma unroll
      for (int j = 0; j < 16; j += 4) {
        float4 v = *(const float4*)(xbase + iblk * 64 + j);
        const uint32_t a = sX + (xih * 16 + j) * 512 + xrw * 4;
        sts32(a, v.x); sts32(a + 512, v.y); sts32(a + 1024, v.z); sts32(a + 1536, v.w);
      }
      __syncthreads();
    }

    // ---- xs broadcasts for this i (identical numerics to R14) ----
    uint32_t xsd[2][2];
    {
      const uint32_t xb = sX + (uint32_t)(i & 63) * 512 + (wm * 32) * 4;
#pragma unroll
      for (int mt = 0; mt < 2; mt++) {
        xsd[mt][0] = dup_h2(lds32(xb + (mt * 16 + g) * 4));
        xsd[mt][1] = dup_h2(lds32(xb + (mt * 16 + g + 8) * 4));
      }
    }

    // next-c W offset (c=4095 prefetches a harmless in-bounds dummy)
    const int c2 = (c + 1) & 4095;
    const size_t noff = (size_t)(c2 & 511) * 512 + (size_t)(c2 >> 9) * 64;

    // ---- LDG ks0,ks1 of c+1 ----
#pragma unroll
    for (int ks = 0; ks < 2; ks++) {
      pv[ks * 4 + 0] = *(const float2*)(wp0 + noff + ks * 16);
      pv[ks * 4 + 1] = *(const float2*)(wp0 + noff + ks * 16 + 8);
      pv[ks * 4 + 2] = *(const float2*)(wp1 + noff + ks * 16);
      pv[ks * 4 + 3] = *(const float2*)(wp1 + noff + ks * 16 + 8);
    }

    // ---- MMA ks0,ks1 (current c) ----
#pragma unroll
    for (int ks = 0; ks < 2; ks++) {
#pragma unroll
      for (int mt = 0; mt < 2; mt++) {
        uint32_t as[4];
        as[0] = hmul2u(yf[mt][ks][0], xsd[mt][0]);
        as[1] = hmul2u(yf[mt][ks][1], xsd[mt][1]);
        as[2] = hmul2u(yf[mt][ks][2], xsd[mt][0]);
        as[3] = hmul2u(yf[mt][ks][3], xsd[mt][1]);
        mma16(acc[mt][0], as, bc[ks * 4 + 0], bc[ks * 4 + 1]);
        mma16(acc[mt][1], as, bc[ks * 4 + 2], bc[ks * 4 + 3]);
      }
    }

    // ---- cvt ks0,ks1 of c+1; LDG ks2,ks3 of c+1 ----
#pragma unroll
    for (int k = 0; k < 8; k++) bc[k] = pack_h2(pv[k].x, pv[k].y);
#pragma unroll
    for (int ks = 2; ks < 4; ks++) {
      pv[(ks - 2) * 4 + 0] = *(const float2*)(wp0 + noff + ks * 16);
      pv[(ks - 2) * 4 + 1] = *(const float2*)(wp0 + noff + ks * 16 + 8);
      pv[(ks - 2) * 4 + 2] = *(const float2*)(wp1 + noff + ks * 16);
      pv[(ks - 2) * 4 + 3] = *(const float2*)(wp1 + noff + ks * 16 + 8);
    }

    // ---- MMA ks2,ks3 (current c) ----
#pragma unroll
    for (int ks = 2; ks < 4; ks++) {
#pragma unroll
      for (int mt = 0; mt < 2; mt++) {
        uint32_t as[4];
        as[0] = hmul2u(yf[mt][ks][0], xsd[mt][0]);
        as[1] = hmul2u(yf[mt][ks][1], xsd[mt][1]);
        as[2] = hmul2u(yf[mt][ks][2], xsd[mt][0]);
        as[3] = hmul2u(yf[mt][ks][3], xsd[mt][1]);
        mma16(acc[mt][0], as, bc[ks * 4 + 0], bc[ks * 4 + 1]);
        mma16(acc[mt][1], as, bc[ks * 4 + 2], bc[ks * 4 + 3]);
      }
    }

    // ---- cvt ks2,ks3 of c+1 ----
#pragma unroll
    for (int k = 0; k < 8; k++) bc[8 + k] = pack_h2(pv[k].x, pv[k].y);

    // ---- bounded RZ chain (64 adds) -> RN fp32 totals ----
    if ((c & 15) == 15) {
#pragma unroll
      for (int mt = 0; mt < 2; mt++)
#pragma unroll
        for (int nt = 0; nt < 2; nt++)
#pragma unroll
          for (int r = 0; r < 4; r++) {
            tot[mt][nt][r] += acc[mt][nt][r];
            acc[mt][nt][r] = 0.f;
          }
    }
  }

  // ---- epilogue: exclusive ownership, non-atomic += ----
#pragma unroll
  for (int mt = 0; mt < 2; mt++)
#pragma unroll
    for (int nt = 0; nt < 2; nt++) {
      const int r0 = b0 + wm * 32 + mt * 16 + g;
      const int c0 = o0 + wn * 16 + nt * 8 + 2 * t;
      out[(size_t)r0 * kOUT + c0]           += tot[mt][nt][0];
      out[(size_t)r0 * kOUT + c0 + 1]       += tot[mt][nt][1];
      out[(size_t)(r0 + 8) * kOUT + c0]     += tot[mt][nt][2];
      out[(size_t)(r0 + 8) * kOUT + c0 + 1] += tot[mt][nt][3];
    }
}

}  // namespace

extern "C" void kernel_launch(void* const* d_in, const int* in_sizes, int n_in,
                              void* d_out, int out_size) {
  (void)in_sizes; (void)n_in; (void)out_size;
  const float* x = (const float*)d_in[0];
  const float* y = (const float*)d_in[1];
  const float* W = (const float*)d_in[2];
  float* out = (float*)d_out;

  cudaFuncSetAttribute(quad_frag, cudaFuncAttributeMaxDynamicSharedMemorySize,
                       F_SMEM);

  cudaMemsetAsync(out, 0, (size_t)1024 * kOUT * sizeof(float));
  lin_pipe<<<dim3(16, 8), 256>>>(x, y, W, out);            // k < 1024
  quad_frag<<<dim3(8, 16), 512, F_SMEM>>>(x, y, W, out);   // bilinear part
}

// round 17
// speedup vs baseline: 1.8728x; 1.8728x over previous
#include <cuda_runtime.h>
#include <cuda_fp16.h>
#include <cstdint>

// out = concat(x, y, outer(x,y)) @ W^T, two kernels:
//  1) lin_pipe  : k < 1024 passthrough (proven).
//  2) quad_fact : bilinear FACTORIZED: out[b,o] += sum_i x[b,i]*(y[b,:]@W_i^T).
//     Memory plan identical to the 2507us R14 kernel (W LDG->STS->ldmatrix,
//     double-buffered 2-i stages, fp32 x-slab, Y fp16 staged once).
//     ARITHMETIC CHANGE: inner loop computes P_i = y @ W_i^T with pure MMA
//     (A = raw register-held Y fragments; the 32 HMUL2/warp/i are GONE), then
//     tot += x[row,i] * P_i via fp32 FFMA. x never rounded to fp16; RZ chains
//     are 4 adds long (flush machinery removed). Expect rel_err ~3e-4.

namespace {

constexpr int    kN1  = 512;
constexpr int    kOUT = 1024;
constexpr size_t kK   = 263168;

__device__ __forceinline__ uint32_t smem_u32(const void* p) {
  uint32_t a;
  asm("{ .reg .u64 t; cvta.to.shared.u64 t, %1; cvt.u32.u64 %0, t; }"
      : "=r"(a) : "l"(p));
  return a;
}
__device__ __forceinline__ void ldx4(uint32_t r[4], uint32_t addr) {
  asm volatile(
      "ldmatrix.sync.aligned.m8n8.x4.shared.b16 {%0,%1,%2,%3}, [%4];"
      : "=r"(r[0]), "=r"(r[1]), "=r"(r[2]), "=r"(r[3]) : "r"(addr));
}
__device__ __forceinline__ void mma16(float c[4], const uint32_t a[4],
                                      uint32_t b0, uint32_t b1) {
  asm volatile(
      "mma.sync.aligned.m16n8k16.row.col.f32.f16.f16.f32 "
      "{%0,%1,%2,%3}, {%4,%5,%6,%7}, {%8,%9}, {%0,%1,%2,%3};"
      : "+f"(c[0]), "+f"(c[1]), "+f"(c[2]), "+f"(c[3])
      : "r"(a[0]), "r"(a[1]), "r"(a[2]), "r"(a[3]), "r"(b0), "r"(b1));
}
__device__ __forceinline__ void sts128(uint32_t a, uint32_t v0, uint32_t v1,
                                       uint32_t v2, uint32_t v3) {
  asm volatile("st.shared.v4.b32 [%0], {%1,%2,%3,%4};"
               :: "r"(a), "r"(v0), "r"(v1), "r"(v2), "r"(v3) : "memory");
}
__device__ __forceinline__ void sts32(uint32_t a, float v) {
  asm volatile("st.shared.f32 [%0], %1;" :: "r"(a), "f"(v) : "memory");
}
__device__ __forceinline__ float lds32(uint32_t a) {
  float v;
  asm volatile("ld.shared.f32 %0, [%1];" : "=f"(v) : "r"(a));
  return v;
}
__device__ __forceinline__ uint32_t pack_h2(float v0, float v1) {
  __half2 h = __floats2half2_rn(v0, v1);
  return *reinterpret_cast<uint32_t*>(&h);
}
__device__ __forceinline__ void split_h2(float v0, float v1, uint32_t& h,
                                         uint32_t& l) {
  __half2 hh = __floats2half2_rn(v0, v1);
  h = *reinterpret_cast<uint32_t*>(&hh);
  l = pack_h2(v0 - __low2float(hh), v1 - __high2float(hh));
}

// ======================= linear part (k<1024): proven pipeline ==============
constexpr int L_LDA = 80, L_SZA = 128 * L_LDA, L_SZW = 128 * L_LDA;
constexpr int L_STAGE = L_SZA + 2 * L_SZW;
constexpr int LNH = 16;

__global__ void __launch_bounds__(256, 1)
lin_pipe(const float* __restrict__ x, const float* __restrict__ y,
         const float* __restrict__ W, float* __restrict__ out) {
  __shared__ __align__(16) uint8_t sm[2 * L_STAGE];
  const uint32_t sb = smem_u32(sm);

  const int tid = threadIdx.x, lane = tid & 31, warp = tid >> 5;
  const int wm = warp >> 2, wn = warp & 3;
  const int b0 = (blockIdx.x >> 1) * 128;
  const int half = blockIdx.x & 1;
  const int o0 = blockIdx.y * 128;
  const int gbase = half * LNH;

  const int prow = tid >> 1, phh = tid & 1;
  const float* __restrict__ xrow = x + (size_t)(b0 + prow) * kN1;
  const float* __restrict__ yrow = y + (size_t)(b0 + prow) * kN1;
  const float* __restrict__ wsrc = W + (size_t)(o0 + prow) * kK + phh * 16;
  const uint32_t pSt = prow * L_LDA + phh * 32;

  const uint32_t aoff =
      (uint32_t)((wm * 64 + (lane & 15)) * L_LDA + (lane >> 4) * 16);
  const uint32_t boff =
      (uint32_t)((wn * 32 + (lane & 7) + ((lane >> 4) & 1) * 8) * L_LDA +
                 ((lane >> 3) & 1) * 16);
  const int g = lane >> 2, t = lane & 3;

  float acc[4][4][4];
#pragma unroll
  for (int mt = 0; mt < 4; mt++)
#pragma unroll
    for (int nt = 0; nt < 4; nt++)
#pragma unroll
      for (int r = 0; r < 4; r++) acc[mt][nt][r] = 0.f;

  float4 av[4], wv[4];

  {  // chunk 0 into stage 0
    const int gc = gbase;
    const float* asrc = (gc < 16) ? (xrow + gc * 32 + phh * 16)
                                  : (yrow + (gc - 16) * 32 + phh * 16);
#pragma unroll
    for (int j = 0; j < 4; j++) av[j] = *(const float4*)(asrc + 4 * j);
    const float* wp = wsrc + (size_t)gc * 32;
#pragma unroll
    for (int j = 0; j < 4; j++) wv[j] = *(const float4*)(wp + 4 * j);

    uint32_t pA[8], pWh[8], pWl[8];
#pragma unroll
    for (int j = 0; j < 4; j++) {
      pA[2 * j]     = pack_h2(av[j].x, av[j].y);
      pA[2 * j + 1] = pack_h2(av[j].z, av[j].w);
      split_h2(wv[j].x, wv[j].y, pWh[2 * j], pWl[2 * j]);
      split_h2(wv[j].z, wv[j].w, pWh[2 * j + 1], pWl[2 * j + 1]);
    }
    sts128(sb + pSt, pA[0], pA[1], pA[2], pA[3]);
    sts128(sb + pSt + 16, pA[4], pA[5], pA[6], pA[7]);
    sts128(sb + L_SZA + pSt, pWh[0], pWh[1], pWh[2], pWh[3]);
    sts128(sb + L_SZA + pSt + 16, pWh[4], pWh[5], pWh[6], pWh[7]);
    sts128(sb + L_SZA + L_SZW + pSt, pWl[0], pWl[1], pWl[2], pWl[3]);
    sts128(sb + L_SZA + L_SZW + pSt + 16, pWl[4], pWl[5], pWl[6], pWl[7]);
  }
  __syncthreads();

  for (int ic = 0; ic < LNH; ic++) {
    const uint32_t rs = sb + (uint32_t)(ic & 1) * L_STAGE;
    const uint32_t ws = sb + (uint32_t)((ic + 1) & 1) * L_STAGE;
    const bool more = (ic + 1 < LNH);

    if (more) {
      const int gc = gbase + ic + 1;
      const float* asrc = (gc < 16) ? (xrow + gc * 32 + phh * 16)
                                    : (yrow + (gc - 16) * 32 + phh * 16);
#pragma unroll
      for (int j = 0; j < 4; j++) av[j] = *(const float4*)(asrc + 4 * j);
      const float* wp = wsrc + (size_t)gc * 32;
#pragma unroll
      for (int j = 0; j < 4; j++) wv[j] = *(const float4*)(wp + 4 * j);
    }

#pragma unroll
    for (int ks = 0; ks < 2; ks++) {
      const uint32_t ko = ks * 32;
      uint32_t aH[4][4], bH[2][4], bL[2][4];
#pragma unroll
      for (int mt = 0; mt < 4; mt++)
        ldx4(aH[mt], rs + aoff + mt * (16 * L_LDA) + ko);
#pragma unroll
      for (int p = 0; p < 2; p++) {
        ldx4(bH[p], rs + L_SZA + boff + p * (16 * L_LDA) + ko);
        ldx4(bL[p], rs + L_SZA + L_SZW + boff + p * (16 * L_LDA) + ko);
      }
#pragma unroll
      for (int mt = 0; mt < 4; mt++)
#pragma unroll
        for (int nt = 0; nt < 4; nt++) {
          const int p = nt >> 1, o = (nt & 1) * 2;
          mma16(acc[mt][nt], aH[mt], bH[p][o], bH[p][o + 1]);
          mma16(acc[mt][nt], aH[mt], bL[p][o], bL[p][o + 1]);
        }
    }

    if (more) {
      uint32_t pA[8], pWh[8], pWl[8];
#pragma unroll
      for (int j = 0; j < 4; j++) {
        pA[2 * j]     = pack_h2(av[j].x, av[j].y);
        pA[2 * j + 1] = pack_h2(av[j].z, av[j].w);
        split_h2(wv[j].x, wv[j].y, pWh[2 * j], pWl[2 * j]);
        split_h2(wv[j].z, wv[j].w, pWh[2 * j + 1], pWl[2 * j + 1]);
      }
      sts128(ws + pSt, pA[0], pA[1], pA[2], pA[3]);
      sts128(ws + pSt + 16, pA[4], pA[5], pA[6], pA[7]);
      sts128(ws + L_SZA + pSt, pWh[0], pWh[1], pWh[2], pWh[3]);
      sts128(ws + L_SZA + pSt + 16, pWh[4], pWh[5], pWh[6], pWh[7]);
      sts128(ws + L_SZA + L_SZW + pSt, pWl[0], pWl[1], pWl[2], pWl[3]);
      sts128(ws + L_SZA + L_SZW + pSt + 16, pWl[4], pWl[5], pWl[6], pWl[7]);
    }
    __syncthreads();
  }

#pragma unroll
  for (int mt = 0; mt < 4; mt++)
#pragma unroll
    for (int nt = 0; nt < 4; nt++) {
      const int r0 = b0 + wm * 64 + mt * 16 + g;
      const int c0 = o0 + wn * 32 + nt * 8 + 2 * t;
      atomicAdd(out + (size_t)r0 * kOUT + c0, acc[mt][nt][0]);
      atomicAdd(out + (size_t)r0 * kOUT + c0 + 1, acc[mt][nt][1]);
      atomicAdd(out + (size_t)(r0 + 8) * kOUT + c0, acc[mt][nt][2]);
      atomicAdd(out + (size_t)(r0 + 8) * kOUT + c0 + 1, acc[mt][nt][3]);
    }
}

// ===== bilinear: R14 memory plan + post-MMA fp32 x-scaling ==================
constexpr int F_LDY  = 1040;
constexpr int F_YH   = 128 * F_LDY;              // 133120
constexpr int F_XS   = 64 * 512;                 // 32768 (64 i x 128 rows fp32)
constexpr int F_LDW  = 144;
constexpr int F_WT   = 64 * F_LDW;               // 9216
constexpr int F_STG  = 2 * F_WT;                 // 2 i's per stage
constexpr int F_SMEM = F_YH + F_XS + 2 * F_STG;  // 202752
constexpr int NSTG   = 2048;

__global__ void __launch_bounds__(512, 1)
quad_fact(const float* __restrict__ x, const float* __restrict__ y,
          const float* __restrict__ W, float* __restrict__ out) {
  extern __shared__ __align__(16) uint8_t dsm[];
  const uint32_t sY = smem_u32(dsm);
  const uint32_t sX = sY + F_YH;
  const uint32_t sW0 = sX + F_XS;

  const int tid = threadIdx.x, lane = tid & 31, warp = tid >> 5;
  const int wm = warp & 3, wn = warp >> 2;  // 4m x 4n, warp tile 32x16
  const int b0 = blockIdx.x * 128, o0 = blockIdx.y * 64;
  const int g = lane >> 2, t = lane & 3;

  // ---- stage Y as fp16 (once) ----
  {
    const int row = tid >> 2, h = tid & 3;
    const float* yr = y + (size_t)(b0 + row) * kN1 + h * 128;
    const uint32_t st = sY + row * F_LDY + h * 256;
#pragma unroll 4
    for (int c = 0; c < 128; c += 8) {
      float4 f0 = *(const float4*)(yr + c);
      float4 f1 = *(const float4*)(yr + c + 4);
      sts128(st + c * 2, pack_h2(f0.x, f0.y), pack_h2(f0.z, f0.w),
             pack_h2(f1.x, f1.y), pack_h2(f1.z, f1.w));
    }
  }

  // ---- W producer: 8 threads per o-row, 8 k-floats each ----
  const int prow = tid >> 3, pq = (tid & 7) * 8;
  const float* __restrict__ wbase = W + (size_t)(o0 + prow) * kK + pq + 1024;
  const uint32_t wSt = prow * F_LDW + pq * 2;

  // ---- x-slab staging: 4 threads/row, 16 i each (fp32) ----
  const int xrw = tid >> 2, xih = tid & 3;
  const float* __restrict__ xbase = x + (size_t)(b0 + xrw) * kN1 + xih * 16;

  const uint32_t aoff =
      (uint32_t)((wm * 32 + (lane & 15)) * F_LDY + (lane >> 4) * 16);
  const uint32_t boff =
      (uint32_t)((wn * 16 + (lane & 7) + ((lane >> 4) & 1) * 8) * F_LDW +
                 ((lane >> 3) & 1) * 16);

  float tot[2][2][4];
#pragma unroll
  for (int mt = 0; mt < 2; mt++)
#pragma unroll
    for (int nt = 0; nt < 2; nt++)
#pragma unroll
      for (int r = 0; r < 4; r++) tot[mt][nt][r] = 0.f;

  // ---- prologue: x-slab iblk 0 + W stage 0 (i = 0 and 1) ----
  {
#pragma unroll
    for (int j = 0; j < 16; j += 4) {
      float4 v = *(const float4*)(xbase + j);
      const uint32_t a = sX + (xih * 16 + j) * 512 + xrw * 4;
      sts32(a, v.x); sts32(a + 512, v.y); sts32(a + 1024, v.z); sts32(a + 1536, v.w);
    }
    float4 a0 = *(const float4*)(wbase);
    float4 a1 = *(const float4*)(wbase + 4);
    float4 b0v = *(const float4*)(wbase + 512);
    float4 b1v = *(const float4*)(wbase + 516);
    sts128(sW0 + wSt, pack_h2(a0.x, a0.y), pack_h2(a0.z, a0.w),
           pack_h2(a1.x, a1.y), pack_h2(a1.z, a1.w));
    sts128(sW0 + F_WT + wSt, pack_h2(b0v.x, b0v.y), pack_h2(b0v.z, b0v.w),
           pack_h2(b1v.x, b1v.y), pack_h2(b1v.z, b1v.w));
  }
  __syncthreads();

  uint32_t yf[2][4][4];  // [mt][ks][reg], RAW y fragments for current jb
  float4 wv[4];          // next-stage W (two i's)

  for (int s = 0; s < NSTG; s++) {
    const int c0i = 2 * s;
    const int jb = c0i >> 9;

    if ((s & 255) == 0) {  // new j-block: reload Y fragments (sY static)
#pragma unroll
      for (int mt = 0; mt < 2; mt++)
#pragma unroll
        for (int ks = 0; ks < 4; ks++)
          ldx4(yf[mt][ks], sY + aoff + jb * 128 + mt * (16 * F_LDY) + ks * 32);
    }
    if ((s & 31) == 0 && s) {  // new 64-i block: restage x-slab
      const int iblk = (c0i & 511) >> 6;
#pragma unroll
      for (int j = 0; j < 16; j += 4) {
        float4 v = *(const float4*)(xbase + iblk * 64 + j);
        const uint32_t a = sX + (xih * 16 + j) * 512 + xrw * 4;
        sts32(a, v.x); sts32(a + 512, v.y); sts32(a + 1024, v.z); sts32(a + 1536, v.w);
      }
      __syncthreads();
    }

    const uint32_t rs = sW0 + (uint32_t)(s & 1) * F_STG;
    const uint32_t ws = sW0 + (uint32_t)((s + 1) & 1) * F_STG;
    const bool more = (s + 1 < NSTG);

    // ---- LDG next stage's W (full MMA phase to land) ----
    if (more) {
      const int c2 = 2 * (s + 1);
      const float* wp = wbase + (size_t)(c2 & 511) * 512 + (c2 >> 9) * 64;
      wv[0] = *(const float4*)(wp);
      wv[1] = *(const float4*)(wp + 4);
      wv[2] = *(const float4*)(wp + 512);
      wv[3] = *(const float4*)(wp + 516);
    }

    // ---- two i's: pure-MMA P_i, then tot += x_i * P_i (fp32 FFMA) ----
#pragma unroll
    for (int u = 0; u < 2; u++) {
      const int i = c0i + u;
      // fp32 x values for this warp's rows (no fp16 rounding of x)
      float xsf[2][2];
      const uint32_t xb = sX + (uint32_t)(i & 63) * 512 + (wm * 32) * 4;
#pragma unroll
      for (int mt = 0; mt < 2; mt++) {
        xsf[mt][0] = lds32(xb + (mt * 16 + g) * 4);
        xsf[mt][1] = lds32(xb + (mt * 16 + g + 8) * 4);
      }

      float pa[2][2][4];
#pragma unroll
      for (int mt = 0; mt < 2; mt++)
#pragma unroll
        for (int nt = 0; nt < 2; nt++)
#pragma unroll
          for (int r = 0; r < 4; r++) pa[mt][nt][r] = 0.f;

      const uint32_t rsu = rs + (uint32_t)u * F_WT;
#pragma unroll
      for (int ks = 0; ks < 4; ks++) {
        uint32_t b[4];
        ldx4(b, rsu + boff + ks * 32);
#pragma unroll
        for (int mt = 0; mt < 2; mt++) {
          mma16(pa[mt][0], yf[mt][ks], b[0], b[1]);
          mma16(pa[mt][1], yf[mt][ks], b[2], b[3]);
        }
      }
#pragma unroll
      for (int mt = 0; mt < 2; mt++)
#pragma unroll
        for (int nt = 0; nt < 2; nt++) {
          tot[mt][nt][0] += xsf[mt][0] * pa[mt][nt][0];
          tot[mt][nt][1] += xsf[mt][0] * pa[mt][nt][1];
          tot[mt][nt][2] += xsf[mt][1] * pa[mt][nt][2];
          tot[mt][nt][3] += xsf[mt][1] * pa[mt][nt][3];
        }
    }

    // ---- STS next stage, then barrier ----
    if (more) {
      sts128(ws + wSt, pack_h2(wv[0].x, wv[0].y), pack_h2(wv[0].z, wv[0].w),
             pack_h2(wv[1].x, wv[1].y), pack_h2(wv[1].z, wv[1].w));
      sts128(ws + F_WT + wSt, pack_h2(wv[2].x, wv[2].y), pack_h2(wv[2].z, wv[2].w),
             pack_h2(wv[3].x, wv[3].y), pack_h2(wv[3].z, wv[3].w));
    }
    __syncthreads();
  }

  // ---- epilogue: exclusive ownership, non-atomic += ----
#pragma unroll
  for (int mt = 0; mt < 2; mt++)
#pragma unroll
    for (int nt = 0; nt < 2; nt++) {
      const int r0 = b0 + wm * 32 + mt * 16 + g;
      const int c0 = o0 + wn * 16 + nt * 8 + 2 * t;
      out[(size_t)r0 * kOUT + c0]           += tot[mt][nt][0];
      out[(size_t)r0 * kOUT + c0 + 1]       += tot[mt][nt][1];
      out[(size_t)(r0 + 8) * kOUT + c0]     += tot[mt][nt][2];
      out[(size_t)(r0 + 8) * kOUT + c0 + 1] += tot[mt][nt][3];
    }
}

}  // namespace

extern "C" void kernel_launch(void* const* d_in, const int* in_sizes, int n_in,
                              void* d_out, int out_size) {
  (void)in_sizes; (void)n_in; (void)out_size;
  const float* x = (const float*)d_in[0];
  const float* y = (const float*)d_in[1];
  const float* W = (const float*)d_in[2];
  float* out = (float*)d_out;

  cudaFuncSetAttribute(quad_fact, cudaFuncAttributeMaxDynamicSharedMemorySize,
                       F_SMEM);

  cudaMemsetAsync(out, 0, (size_t)1024 * kOUT * sizeof(float));
  lin_pipe<<<dim3(16, 8), 256>>>(x, y, W, out);            // k < 1024
  quad_fact<<<dim3(8, 16), 512, F_SMEM>>>(x, y, W, out);   // bilinear part
}